// round 16
// baseline (speedup 1.0000x reference)
#include <cuda_runtime.h>
#include <cuda_fp16.h>
#include <cstdint>

// Problem constants (from reference)
#define N_NODES 50000
#define N_EDGES 800000
#define D_IN    128
#define D_OUT   128

// Scratch: support = X @ W stored as fp16 (12.8 MB).
__device__ __half g_support[(size_t)N_NODES * D_OUT];
// CSR row pointers built from the sorted adj_dst (200 KB).
__device__ int g_row_ptr[N_NODES + 1];

// ---------------------------------------------------------------------------
// Kernel 1: fp16 tensor-core GEMM + fused CSR row_ptr build.
// (unchanged from the measured ~15.8us configuration)
// ---------------------------------------------------------------------------
#define BM    128
#define BKT   64
#define APADH 8
#define BPADH 8

#define GEMM_GRID    ((N_NODES + BM - 1) / BM)      // 391
#define GEMM_NTHREAD (GEMM_GRID * 256)              // 100096
#define N_GROUPS     (N_EDGES / 4)                  // 200000

__device__ __forceinline__ uint32_t smem_u32(const void* p) {
    return (uint32_t)__cvta_generic_to_shared(p);
}

__device__ __forceinline__ void ldm_x4(uint32_t* r, const void* p) {
    uint32_t a = smem_u32(p);
    asm volatile("ldmatrix.sync.aligned.m8n8.x4.shared.b16 {%0,%1,%2,%3}, [%4];"
                 : "=r"(r[0]), "=r"(r[1]), "=r"(r[2]), "=r"(r[3]) : "r"(a));
}

__device__ __forceinline__ void ldm_x4_trans(uint32_t* r, const void* p) {
    uint32_t a = smem_u32(p);
    asm volatile("ldmatrix.sync.aligned.m8n8.x4.trans.shared.b16 {%0,%1,%2,%3}, [%4];"
                 : "=r"(r[0]), "=r"(r[1]), "=r"(r[2]), "=r"(r[3]) : "r"(a));
}

__device__ __forceinline__ void mma_f16(float* c, const uint32_t* a,
                                        uint32_t b0, uint32_t b1) {
    asm volatile(
        "mma.sync.aligned.m16n8k16.row.col.f32.f16.f16.f32 "
        "{%0,%1,%2,%3}, {%4,%5,%6,%7}, {%8,%9}, {%0,%1,%2,%3};\n"
        : "+f"(c[0]), "+f"(c[1]), "+f"(c[2]), "+f"(c[3])
        : "r"(a[0]), "r"(a[1]), "r"(a[2]), "r"(a[3]), "r"(b0), "r"(b1));
}

__device__ __forceinline__ uint2 f4_to_h4(float4 a) {
    __half2 h0 = __floats2half2_rn(a.x, a.y);
    __half2 h1 = __floats2half2_rn(a.z, a.w);
    return make_uint2(*(uint32_t*)&h0, *(uint32_t*)&h1);
}

__device__ __forceinline__ int clamp_node(int d) {
    if (d < 0) d = 0;
    if (d > N_NODES - 1) d = N_NODES - 1;
    return d;
}

__device__ __forceinline__ void rowptr_group(const int* __restrict__ dst, int t) {
    const int e = t * 4;
    int4 d4 = *(const int4*)&dst[e];
    int d0 = clamp_node(d4.x), d1 = clamp_node(d4.y);
    int d2 = clamp_node(d4.z), d3 = clamp_node(d4.w);

    int dprev = (e == 0) ? -1 : clamp_node(dst[e - 1]);

    for (int n = dprev + 1; n <= d0; n++) g_row_ptr[n] = e;
    for (int n = d0 + 1;    n <= d1; n++) g_row_ptr[n] = e + 1;
    for (int n = d1 + 1;    n <= d2; n++) g_row_ptr[n] = e + 2;
    for (int n = d2 + 1;    n <= d3; n++) g_row_ptr[n] = e + 3;
    if (e + 4 == N_EDGES) {
        for (int n = d3 + 1; n <= N_NODES; n++) g_row_ptr[n] = N_EDGES;
    }
}

__global__ __launch_bounds__(256, 2) void gemm_tc_kernel(const float* __restrict__ X,
                                                         const float* __restrict__ W,
                                                         const int* __restrict__ dst) {
    __shared__ __half As[BM][BKT + APADH];     // 128 x 72 halves
    __shared__ __half Bs[BKT][D_OUT + BPADH];  // 64 x 136 halves

    const int tid  = threadIdx.x;
    const int wid  = tid >> 5;
    const int lane = tid & 31;
    const int block_row = blockIdx.x * BM;

    const int warp_m = (wid & 3) * 32;
    const int warp_n = (wid >> 2) * 64;
    const int lq = lane >> 2;
    const int lr = lane & 3;
    const int quad = lane >> 3;
    const int rin  = lane & 7;

    float acc[2][8][4];
#pragma unroll
    for (int mt = 0; mt < 2; mt++)
#pragma unroll
        for (int nt = 0; nt < 8; nt++)
#pragma unroll
            for (int i = 0; i < 4; i++) acc[mt][nt][i] = 0.0f;

    uint2 aH[8], bH[8];

#pragma unroll
    for (int i = 0; i < 8; i++) {
        int idx = tid + i * 256;
        int ar  = idx >> 4;
        int ac4 = idx & 15;
        int grow = block_row + ar;
        float4 a = (grow < N_NODES)
            ? *(const float4*)&X[(size_t)grow * D_IN + ac4 * 4]
            : make_float4(0.f, 0.f, 0.f, 0.f);
        aH[i] = f4_to_h4(a);
        int br  = idx >> 5;
        int bc4 = idx & 31;
        bH[i] = f4_to_h4(*(const float4*)&W[(size_t)br * D_OUT + bc4 * 4]);
    }

    // Fused rowptr build (independent work; overlaps prefetch latency).
    {
        int g = blockIdx.x * 256 + tid;
        rowptr_group(dst, g);
        int g2 = g + GEMM_NTHREAD;
        if (g2 < N_GROUPS) rowptr_group(dst, g2);
    }

#pragma unroll 1
    for (int kb = 0; kb < D_IN / BKT; kb++) {
#pragma unroll
        for (int i = 0; i < 8; i++) {
            int idx = tid + i * 256;
            int ar  = idx >> 4;
            int ac  = (idx & 15) * 4;
            *(uint2*)&As[ar][ac] = aH[i];
            int br  = idx >> 5;
            int bc  = (idx & 31) * 4;
            *(uint2*)&Bs[br][bc] = bH[i];
        }
        __syncthreads();

        if (kb + 1 < D_IN / BKT) {
            int k0 = (kb + 1) * BKT;
#pragma unroll
            for (int i = 0; i < 8; i++) {
                int idx = tid + i * 256;
                int ar  = idx >> 4;
                int ac4 = idx & 15;
                int grow = block_row + ar;
                float4 a = (grow < N_NODES)
                    ? *(const float4*)&X[(size_t)grow * D_IN + k0 + ac4 * 4]
                    : make_float4(0.f, 0.f, 0.f, 0.f);
                aH[i] = f4_to_h4(a);
                int br  = idx >> 5;
                int bc4 = idx & 31;
                bH[i] = f4_to_h4(*(const float4*)&W[(size_t)(k0 + br) * D_OUT + bc4 * 4]);
            }
        }

#pragma unroll
        for (int ks = 0; ks < 4; ks++) {
            const int k0 = ks * 16;

            uint32_t af[2][4];
#pragma unroll
            for (int mt = 0; mt < 2; mt++) {
                const __half* p =
                    &As[warp_m + mt * 16 + (quad & 1) * 8 + rin][k0 + (quad >> 1) * 8];
                ldm_x4(af[mt], p);
            }

            uint32_t bf[8][2];
#pragma unroll
            for (int np = 0; np < 4; np++) {
                uint32_t r[4];
                const __half* p =
                    &Bs[k0 + (quad & 1) * 8 + rin][warp_n + np * 16 + (quad >> 1) * 8];
                ldm_x4_trans(r, p);
                bf[np * 2    ][0] = r[0];
                bf[np * 2    ][1] = r[1];
                bf[np * 2 + 1][0] = r[2];
                bf[np * 2 + 1][1] = r[3];
            }

#pragma unroll
            for (int nt = 0; nt < 8; nt++) {
                mma_f16(acc[0][nt], af[0], bf[nt][0], bf[nt][1]);
                mma_f16(acc[1][nt], af[1], bf[nt][0], bf[nt][1]);
            }
        }
        __syncthreads();
    }

#pragma unroll
    for (int mt = 0; mt < 2; mt++) {
        int r0 = block_row + warp_m + mt * 16 + lq;
        int r1 = r0 + 8;
#pragma unroll
        for (int nt = 0; nt < 8; nt++) {
            int c = warp_n + nt * 8 + lr * 2;
            if (r0 < N_NODES)
                *(__half2*)&g_support[(size_t)r0 * D_OUT + c] =
                    __floats2half2_rn(acc[mt][nt][0], acc[mt][nt][1]);
            if (r1 < N_NODES)
                *(__half2*)&g_support[(size_t)r1 * D_OUT + c] =
                    __floats2half2_rn(acc[mt][nt][2], acc[mt][nt][3]);
        }
    }
}

// ---------------------------------------------------------------------------
// Kernel 2: CSR SpMM — latency-exposure restructure (R15 ncu: nothing
// saturated -> exposed-latency bound).  Changes vs R15:
//  * 4 consecutive nodes per warp: row_ptr (5 boundaries) loaded once as
//    int4+int -> warp-startup DRAM latency amortized 4x; 12500 warps.
//  * batch-8 gathers (MLP 4 -> 8): an average row is 2 serial L2 round
//    trips instead of 4.
// ---------------------------------------------------------------------------
#define NODES_PER_WARP 4

__device__ __forceinline__ void edge_accum(float4& acc, uint2 g, float v) {
    float2 f0 = __half22float2(*(const __half2*)&g.x);
    float2 f1 = __half22float2(*(const __half2*)&g.y);
    acc.x += v * f0.x;
    acc.y += v * f0.y;
    acc.z += v * f1.x;
    acc.w += v * f1.y;
}

__global__ __launch_bounds__(256) void spmm_csr_kernel(const int* __restrict__ src,
                                                       const float* __restrict__ val,
                                                       const float* __restrict__ bias,
                                                       float* __restrict__ out) {
    const int warp_id = (blockIdx.x * blockDim.x + threadIdx.x) >> 5;
    const int lane    = threadIdx.x & 31;
    const unsigned lane4 = lane * 4;

    const int node0 = warp_id * NODES_PER_WARP;
    if (node0 >= N_NODES) return;

    // One vector load covers 4 row boundaries; 5th is scalar. node0 % 4 == 0
    // so &g_row_ptr[node0] is 16B-aligned.
    int rp[NODES_PER_WARP + 1];
    {
        int4 r4 = *(const int4*)&g_row_ptr[node0];
        rp[0] = r4.x; rp[1] = r4.y; rp[2] = r4.z; rp[3] = r4.w;
        rp[4] = g_row_ptr[node0 + 4];
    }

    const float4 bias4 = *(const float4*)&bias[lane4];

#pragma unroll 1
    for (int r = 0; r < NODES_PER_WARP; r++) {
        const int n  = node0 + r;
        const int r0 = rp[r];
        const int r1 = rp[r + 1];

        float4 acc = make_float4(0.f, 0.f, 0.f, 0.f);

        int e = r0;
        // Scalar prologue to a 4-aligned edge index (<= 3 iterations).
        int e_al = (r0 + 3) & ~3;
        if (e_al > r1) e_al = r1;
        for (; e < e_al; e++) {
            unsigned off = (unsigned)src[e] * D_OUT + lane4;
            uint2 g = *(const uint2*)&g_support[off];
            edge_accum(acc, g, val[e]);
        }
        // Batches of 8: 8 independent gathers in flight.
        for (; e + 8 <= r1; e += 8) {
            const int4   sa = *(const int4*)&src[e];
            const int4   sb = *(const int4*)&src[e + 4];
            const float4 va = *(const float4*)&val[e];
            const float4 vb = *(const float4*)&val[e + 4];

            unsigned o0 = (unsigned)sa.x * D_OUT + lane4;
            unsigned o1 = (unsigned)sa.y * D_OUT + lane4;
            unsigned o2 = (unsigned)sa.z * D_OUT + lane4;
            unsigned o3 = (unsigned)sa.w * D_OUT + lane4;
            unsigned o4 = (unsigned)sb.x * D_OUT + lane4;
            unsigned o5 = (unsigned)sb.y * D_OUT + lane4;
            unsigned o6 = (unsigned)sb.z * D_OUT + lane4;
            unsigned o7 = (unsigned)sb.w * D_OUT + lane4;

            uint2 g0 = *(const uint2*)&g_support[o0];
            uint2 g1 = *(const uint2*)&g_support[o1];
            uint2 g2 = *(const uint2*)&g_support[o2];
            uint2 g3 = *(const uint2*)&g_support[o3];
            uint2 g4 = *(const uint2*)&g_support[o4];
            uint2 g5 = *(const uint2*)&g_support[o5];
            uint2 g6 = *(const uint2*)&g_support[o6];
            uint2 g7 = *(const uint2*)&g_support[o7];

            edge_accum(acc, g0, va.x);
            edge_accum(acc, g1, va.y);
            edge_accum(acc, g2, va.z);
            edge_accum(acc, g3, va.w);
            edge_accum(acc, g4, vb.x);
            edge_accum(acc, g5, vb.y);
            edge_accum(acc, g6, vb.z);
            edge_accum(acc, g7, vb.w);
        }
        // Batch of 4.
        for (; e + 4 <= r1; e += 4) {
            const int4   s4 = *(const int4*)&src[e];
            const float4 v4 = *(const float4*)&val[e];

            unsigned o0 = (unsigned)s4.x * D_OUT + lane4;
            unsigned o1 = (unsigned)s4.y * D_OUT + lane4;
            unsigned o2 = (unsigned)s4.z * D_OUT + lane4;
            unsigned o3 = (unsigned)s4.w * D_OUT + lane4;

            uint2 g0 = *(const uint2*)&g_support[o0];
            uint2 g1 = *(const uint2*)&g_support[o1];
            uint2 g2 = *(const uint2*)&g_support[o2];
            uint2 g3 = *(const uint2*)&g_support[o3];

            edge_accum(acc, g0, v4.x);
            edge_accum(acc, g1, v4.y);
            edge_accum(acc, g2, v4.z);
            edge_accum(acc, g3, v4.w);
        }
        // Scalar tail.
        for (; e < r1; e++) {
            unsigned off = (unsigned)src[e] * D_OUT + lane4;
            uint2 g = *(const uint2*)&g_support[off];
            edge_accum(acc, g, val[e]);
        }

        *(float4*)&out[(size_t)n * D_OUT + lane4] =
            make_float4(acc.x + bias4.x, acc.y + bias4.y,
                        acc.z + bias4.z, acc.w + bias4.w);
    }
}

// ---------------------------------------------------------------------------
// Launch
// Inputs (metadata order): x, adj_src, adj_dst, adj_val, weight, bias
// ---------------------------------------------------------------------------
extern "C" void kernel_launch(void* const* d_in, const int* in_sizes, int n_in,
                              void* d_out, int out_size) {
    const float* x      = (const float*)d_in[0];
    const int*   adjsrc = (const int*)d_in[1];
    const int*   adjdst = (const int*)d_in[2];
    const float* adjval = (const float*)d_in[3];
    const float* weight = (const float*)d_in[4];
    const float* bias   = (const float*)d_in[5];
    float*       out    = (float*)d_out;

    // 1) support = X @ W (fp16 tensor cores) + fused rowptr build
    gemm_tc_kernel<<<GEMM_GRID, 256>>>(x, weight, adjdst);

    // 2) out[n,:] = bias + CSR-row reduction  (one warp per 4 nodes)
    int n_warps  = (N_NODES + NODES_PER_WARP - 1) / NODES_PER_WARP;  // 12500
    int n_blocks = (n_warps * 32 + 255) / 256;                       // 1563
    spmm_csr_kernel<<<n_blocks, 256>>>(adjsrc, adjval, bias, out);
}

// round 17
// speedup vs baseline: 1.0443x; 1.0443x over previous
#include <cuda_runtime.h>
#include <cuda_fp16.h>
#include <cstdint>

// Problem constants (from reference)
#define N_NODES 50000
#define N_EDGES 800000
#define D_IN    128
#define D_OUT   128

// Scratch: support = X @ W stored as fp16 (12.8 MB).
__device__ __half g_support[(size_t)N_NODES * D_OUT];
// CSR row pointers built from the sorted adj_dst (200 KB).
__device__ int g_row_ptr[N_NODES + 1];

// ---------------------------------------------------------------------------
// Kernel 1: fp16 tensor-core GEMM + fused CSR row_ptr build.
// (unchanged from the measured ~15.8us configuration)
// ---------------------------------------------------------------------------
#define BM    128
#define BKT   64
#define APADH 8
#define BPADH 8

#define GEMM_GRID    ((N_NODES + BM - 1) / BM)      // 391
#define GEMM_NTHREAD (GEMM_GRID * 256)              // 100096
#define N_GROUPS     (N_EDGES / 4)                  // 200000

__device__ __forceinline__ uint32_t smem_u32(const void* p) {
    return (uint32_t)__cvta_generic_to_shared(p);
}

__device__ __forceinline__ void ldm_x4(uint32_t* r, const void* p) {
    uint32_t a = smem_u32(p);
    asm volatile("ldmatrix.sync.aligned.m8n8.x4.shared.b16 {%0,%1,%2,%3}, [%4];"
                 : "=r"(r[0]), "=r"(r[1]), "=r"(r[2]), "=r"(r[3]) : "r"(a));
}

__device__ __forceinline__ void ldm_x4_trans(uint32_t* r, const void* p) {
    uint32_t a = smem_u32(p);
    asm volatile("ldmatrix.sync.aligned.m8n8.x4.trans.shared.b16 {%0,%1,%2,%3}, [%4];"
                 : "=r"(r[0]), "=r"(r[1]), "=r"(r[2]), "=r"(r[3]) : "r"(a));
}

__device__ __forceinline__ void mma_f16(float* c, const uint32_t* a,
                                        uint32_t b0, uint32_t b1) {
    asm volatile(
        "mma.sync.aligned.m16n8k16.row.col.f32.f16.f16.f32 "
        "{%0,%1,%2,%3}, {%4,%5,%6,%7}, {%8,%9}, {%0,%1,%2,%3};\n"
        : "+f"(c[0]), "+f"(c[1]), "+f"(c[2]), "+f"(c[3])
        : "r"(a[0]), "r"(a[1]), "r"(a[2]), "r"(a[3]), "r"(b0), "r"(b1));
}

__device__ __forceinline__ uint2 f4_to_h4(float4 a) {
    __half2 h0 = __floats2half2_rn(a.x, a.y);
    __half2 h1 = __floats2half2_rn(a.z, a.w);
    return make_uint2(*(uint32_t*)&h0, *(uint32_t*)&h1);
}

__device__ __forceinline__ int clamp_node(int d) {
    if (d < 0) d = 0;
    if (d > N_NODES - 1) d = N_NODES - 1;
    return d;
}

__device__ __forceinline__ void rowptr_group(const int* __restrict__ dst, int t) {
    const int e = t * 4;
    int4 d4 = *(const int4*)&dst[e];
    int d0 = clamp_node(d4.x), d1 = clamp_node(d4.y);
    int d2 = clamp_node(d4.z), d3 = clamp_node(d4.w);

    int dprev = (e == 0) ? -1 : clamp_node(dst[e - 1]);

    for (int n = dprev + 1; n <= d0; n++) g_row_ptr[n] = e;
    for (int n = d0 + 1;    n <= d1; n++) g_row_ptr[n] = e + 1;
    for (int n = d1 + 1;    n <= d2; n++) g_row_ptr[n] = e + 2;
    for (int n = d2 + 1;    n <= d3; n++) g_row_ptr[n] = e + 3;
    if (e + 4 == N_EDGES) {
        for (int n = d3 + 1; n <= N_NODES; n++) g_row_ptr[n] = N_EDGES;
    }
}

__global__ __launch_bounds__(256, 2) void gemm_tc_kernel(const float* __restrict__ X,
                                                         const float* __restrict__ W,
                                                         const int* __restrict__ dst) {
    __shared__ __half As[BM][BKT + APADH];     // 128 x 72 halves
    __shared__ __half Bs[BKT][D_OUT + BPADH];  // 64 x 136 halves

    const int tid  = threadIdx.x;
    const int wid  = tid >> 5;
    const int lane = tid & 31;
    const int block_row = blockIdx.x * BM;

    const int warp_m = (wid & 3) * 32;
    const int warp_n = (wid >> 2) * 64;
    const int lq = lane >> 2;
    const int lr = lane & 3;
    const int quad = lane >> 3;
    const int rin  = lane & 7;

    float acc[2][8][4];
#pragma unroll
    for (int mt = 0; mt < 2; mt++)
#pragma unroll
        for (int nt = 0; nt < 8; nt++)
#pragma unroll
            for (int i = 0; i < 4; i++) acc[mt][nt][i] = 0.0f;

    uint2 aH[8], bH[8];

#pragma unroll
    for (int i = 0; i < 8; i++) {
        int idx = tid + i * 256;
        int ar  = idx >> 4;
        int ac4 = idx & 15;
        int grow = block_row + ar;
        float4 a = (grow < N_NODES)
            ? *(const float4*)&X[(size_t)grow * D_IN + ac4 * 4]
            : make_float4(0.f, 0.f, 0.f, 0.f);
        aH[i] = f4_to_h4(a);
        int br  = idx >> 5;
        int bc4 = idx & 31;
        bH[i] = f4_to_h4(*(const float4*)&W[(size_t)br * D_OUT + bc4 * 4]);
    }

    // Fused rowptr build (independent work; overlaps prefetch latency).
    {
        int g = blockIdx.x * 256 + tid;
        rowptr_group(dst, g);
        int g2 = g + GEMM_NTHREAD;
        if (g2 < N_GROUPS) rowptr_group(dst, g2);
    }

#pragma unroll 1
    for (int kb = 0; kb < D_IN / BKT; kb++) {
#pragma unroll
        for (int i = 0; i < 8; i++) {
            int idx = tid + i * 256;
            int ar  = idx >> 4;
            int ac  = (idx & 15) * 4;
            *(uint2*)&As[ar][ac] = aH[i];
            int br  = idx >> 5;
            int bc  = (idx & 31) * 4;
            *(uint2*)&Bs[br][bc] = bH[i];
        }
        __syncthreads();

        if (kb + 1 < D_IN / BKT) {
            int k0 = (kb + 1) * BKT;
#pragma unroll
            for (int i = 0; i < 8; i++) {
                int idx = tid + i * 256;
                int ar  = idx >> 4;
                int ac4 = idx & 15;
                int grow = block_row + ar;
                float4 a = (grow < N_NODES)
                    ? *(const float4*)&X[(size_t)grow * D_IN + k0 + ac4 * 4]
                    : make_float4(0.f, 0.f, 0.f, 0.f);
                aH[i] = f4_to_h4(a);
                int br  = idx >> 5;
                int bc4 = idx & 31;
                bH[i] = f4_to_h4(*(const float4*)&W[(size_t)(k0 + br) * D_OUT + bc4 * 4]);
            }
        }

#pragma unroll
        for (int ks = 0; ks < 4; ks++) {
            const int k0 = ks * 16;

            uint32_t af[2][4];
#pragma unroll
            for (int mt = 0; mt < 2; mt++) {
                const __half* p =
                    &As[warp_m + mt * 16 + (quad & 1) * 8 + rin][k0 + (quad >> 1) * 8];
                ldm_x4(af[mt], p);
            }

            uint32_t bf[8][2];
#pragma unroll
            for (int np = 0; np < 4; np++) {
                uint32_t r[4];
                const __half* p =
                    &Bs[k0 + (quad & 1) * 8 + rin][warp_n + np * 16 + (quad >> 1) * 8];
                ldm_x4_trans(r, p);
                bf[np * 2    ][0] = r[0];
                bf[np * 2    ][1] = r[1];
                bf[np * 2 + 1][0] = r[2];
                bf[np * 2 + 1][1] = r[3];
            }

#pragma unroll
            for (int nt = 0; nt < 8; nt++) {
                mma_f16(acc[0][nt], af[0], bf[nt][0], bf[nt][1]);
                mma_f16(acc[1][nt], af[1], bf[nt][0], bf[nt][1]);
            }
        }
        __syncthreads();
    }

#pragma unroll
    for (int mt = 0; mt < 2; mt++) {
        int r0 = block_row + warp_m + mt * 16 + lq;
        int r1 = r0 + 8;
#pragma unroll
        for (int nt = 0; nt < 8; nt++) {
            int c = warp_n + nt * 8 + lr * 2;
            if (r0 < N_NODES)
                *(__half2*)&g_support[(size_t)r0 * D_OUT + c] =
                    __floats2half2_rn(acc[mt][nt][0], acc[mt][nt][1]);
            if (r1 < N_NODES)
                *(__half2*)&g_support[(size_t)r1 * D_OUT + c] =
                    __floats2half2_rn(acc[mt][nt][2], acc[mt][nt][3]);
        }
    }
}

// ---------------------------------------------------------------------------
// Kernel 2: CSR SpMM with CTA-cooperative metadata staging.
// R16 lesson: never trade resident-warp count for per-warp efficiency.
// Keep warp-per-node (50K warps), but the CTA (8 warps = 8 consecutive
// nodes = one contiguous edge slice, mean 128 edges) stages src/val into
// smem with coalesced loads issued all at once. The per-warp inner chain
// becomes LDS(29) -> gather(~250) instead of LDG(300-600) -> gather, and
// batch-8 gathers make an average row 2 short serial rounds.
// Capacity fallback keeps correctness independent of degree distribution.
// ---------------------------------------------------------------------------
#define NODES_PER_CTA 8
#define STAGE_CAP     512   // mean 128, sigma ~11 -> overflow essentially never

__device__ __forceinline__ void edge_accum(float4& acc, uint2 g, float v) {
    float2 f0 = __half22float2(*(const __half2*)&g.x);
    float2 f1 = __half22float2(*(const __half2*)&g.y);
    acc.x += v * f0.x;
    acc.y += v * f0.y;
    acc.z += v * f1.x;
    acc.w += v * f1.y;
}

__global__ __launch_bounds__(256) void spmm_csr_kernel(const int* __restrict__ src,
                                                       const float* __restrict__ val,
                                                       const float* __restrict__ bias,
                                                       float* __restrict__ out) {
    __shared__ int   s_src[STAGE_CAP];
    __shared__ float s_val[STAGE_CAP];
    __shared__ int   s_rp[NODES_PER_CTA + 1];

    const int tid  = threadIdx.x;
    const int wid  = tid >> 5;
    const int lane = tid & 31;
    const unsigned lane4 = lane * 4;
    const int node0 = blockIdx.x * NODES_PER_CTA;   // grid exactly covers 50000

    if (tid <= NODES_PER_CTA)
        s_rp[tid] = g_row_ptr[node0 + tid];
    __syncthreads();

    const int er0   = s_rp[0];
    const int count = s_rp[NODES_PER_CTA] - er0;
    const bool staged = (count <= STAGE_CAP);

    if (staged) {
        for (int i = tid; i < count; i += 256) {
            s_src[i] = src[er0 + i];
            s_val[i] = val[er0 + i];
        }
    }
    __syncthreads();

    const int n  = node0 + wid;
    const int r0 = s_rp[wid];
    const int r1 = s_rp[wid + 1];

    const float4 bias4 = *(const float4*)&bias[lane4];
    float4 acc = make_float4(0.f, 0.f, 0.f, 0.f);

    if (staged) {
        int i    = r0 - er0;
        int iend = r1 - er0;
        // Batch-8: 8 independent gathers in flight; metadata from smem.
        for (; i + 8 <= iend; i += 8) {
            unsigned o[8];
#pragma unroll
            for (int j = 0; j < 8; j++)
                o[j] = (unsigned)s_src[i + j] * D_OUT + lane4;
            uint2 g[8];
#pragma unroll
            for (int j = 0; j < 8; j++)
                g[j] = *(const uint2*)&g_support[o[j]];
#pragma unroll
            for (int j = 0; j < 8; j++)
                edge_accum(acc, g[j], s_val[i + j]);
        }
        // Batch-4.
        for (; i + 4 <= iend; i += 4) {
            unsigned o[4];
#pragma unroll
            for (int j = 0; j < 4; j++)
                o[j] = (unsigned)s_src[i + j] * D_OUT + lane4;
            uint2 g[4];
#pragma unroll
            for (int j = 0; j < 4; j++)
                g[j] = *(const uint2*)&g_support[o[j]];
#pragma unroll
            for (int j = 0; j < 4; j++)
                edge_accum(acc, g[j], s_val[i + j]);
        }
        // Scalar tail.
        for (; i < iend; i++) {
            unsigned o = (unsigned)s_src[i] * D_OUT + lane4;
            uint2 g = *(const uint2*)&g_support[o];
            edge_accum(acc, g, s_val[i]);
        }
    } else {
        // Fallback (degree spike beyond STAGE_CAP): global metadata, batch-4.
        int e = r0;
        int e_al = (r0 + 3) & ~3;
        if (e_al > r1) e_al = r1;
        for (; e < e_al; e++) {
            unsigned o = (unsigned)src[e] * D_OUT + lane4;
            uint2 g = *(const uint2*)&g_support[o];
            edge_accum(acc, g, val[e]);
        }
        for (; e + 4 <= r1; e += 4) {
            const int4   s4 = *(const int4*)&src[e];
            const float4 v4 = *(const float4*)&val[e];
            unsigned o0 = (unsigned)s4.x * D_OUT + lane4;
            unsigned o1 = (unsigned)s4.y * D_OUT + lane4;
            unsigned o2 = (unsigned)s4.z * D_OUT + lane4;
            unsigned o3 = (unsigned)s4.w * D_OUT + lane4;
            uint2 g0 = *(const uint2*)&g_support[o0];
            uint2 g1 = *(const uint2*)&g_support[o1];
            uint2 g2 = *(const uint2*)&g_support[o2];
            uint2 g3 = *(const uint2*)&g_support[o3];
            edge_accum(acc, g0, v4.x);
            edge_accum(acc, g1, v4.y);
            edge_accum(acc, g2, v4.z);
            edge_accum(acc, g3, v4.w);
        }
        for (; e < r1; e++) {
            unsigned o = (unsigned)src[e] * D_OUT + lane4;
            uint2 g = *(const uint2*)&g_support[o];
            edge_accum(acc, g, val[e]);
        }
    }

    *(float4*)&out[(size_t)n * D_OUT + lane4] =
        make_float4(acc.x + bias4.x, acc.y + bias4.y,
                    acc.z + bias4.z, acc.w + bias4.w);
}

// ---------------------------------------------------------------------------
// Launch
// Inputs (metadata order): x, adj_src, adj_dst, adj_val, weight, bias
// ---------------------------------------------------------------------------
extern "C" void kernel_launch(void* const* d_in, const int* in_sizes, int n_in,
                              void* d_out, int out_size) {
    const float* x      = (const float*)d_in[0];
    const int*   adjsrc = (const int*)d_in[1];
    const int*   adjdst = (const int*)d_in[2];
    const float* adjval = (const float*)d_in[3];
    const float* weight = (const float*)d_in[4];
    const float* bias   = (const float*)d_in[5];
    float*       out    = (float*)d_out;

    // 1) support = X @ W (fp16 tensor cores) + fused rowptr build
    gemm_tc_kernel<<<GEMM_GRID, 256>>>(x, weight, adjdst);

    // 2) out[n,:] = bias + CSR-row reduction
    //    (one warp per node; CTA stages metadata for its 8 nodes)
    int n_blocks = N_NODES / NODES_PER_CTA;   // 6250
    spmm_csr_kernel<<<n_blocks, 256>>>(adjsrc, adjval, bias, out);
}